// round 3
// baseline (speedup 1.0000x reference)
#include <cuda_runtime.h>

// Problem shapes (fixed by the dataset)
#define B_  1024
#define V_  50000
#define E_  256
#define L_  17

// Split-K GEMM config: grid = 8 x 2 x 37 = 592 CTAs = 2 exact waves of 296
#define SPLITS   37
#define KCHUNK   1360          // 85 BK-steps; last split: 50000-36*1360=1040 (65 steps)
#define BM       128
#define BN       128
#define BK       16

// Scratch: split-K partials [SPLITS][B][E], and reduced embedding [B][E].
__device__ __align__(128) float g_scratch[SPLITS * B_ * E_];
__device__ __align__(128) float g_emb[B_ * E_];

// Packed f32x2 FMA: d.lo += a.lo*b.lo; d.hi += a.hi*b.hi  (exact fp32 FMA x2)
#define FFMA2(d, a, b) \
    asm("fma.rn.f32x2 %0, %1, %2, %0;" : "+l"(d) : "l"(a), "l"(b))

#define DUP_F32X2(d, s) \
    asm("mov.b64 %0, {%1, %1};" : "=l"(d) : "f"(s))

// ---------------------------------------------------------------------------
// Kernel 1: split-K FP32 SGEMM via packed fma.rn.f32x2.
// x: [B, V] row-major, W: [E, V] row-major -> K-contiguous NT GEMM.
// Block tile 128x128, BK=16, 128 threads, 8m x 16n per-thread microtile
// (stored as 8x8 packed f32x2 accumulators, pairs along n).
// ---------------------------------------------------------------------------
__global__ __launch_bounds__(128, 2) void gemm_splitk_kernel(
    const float* __restrict__ x, const float* __restrict__ W)
{
    __shared__ float As[BK][BM];   // k-major
    __shared__ float Bs[BK][BN];

    const int tid   = threadIdx.x;
    const int brow  = blockIdx.x;          // 0..7   (B tiles)
    const int bcol  = blockIdx.y;          // 0..1   (E tiles)
    const int split = blockIdx.z;          // 0..36
    const int kbase = split * KCHUNK;
    const int nsteps = (split == SPLITS - 1) ? (50000 - (SPLITS - 1) * KCHUNK) / BK
                                             : KCHUNK / BK;

    const int trm = tid >> 3;              // 0..15  (m groups of 8)
    const int tcn = tid & 7;               // 0..7   (n groups of 16)
    const int m0  = trm * 8;
    const int n0  = tcn * 16;

    // global-load mapping: tile is 128 rows x 16 k-floats = 512 float4,
    // 128 threads -> 4 float4 each per operand.
    int lr[4], lk[4];
#pragma unroll
    for (int i = 0; i < 4; i++) {
        const int f = tid + i * 128;
        lr[i] = f >> 2;
        lk[i] = (f & 3) * 4;
    }

    const float* xg = x + (size_t)(brow * BM) * V_ + kbase;
    const float* wg = W + (size_t)(bcol * BN) * V_ + kbase;

    // 8x16 f32 microtile as 8x8 packed f32x2 (pairs along n)
    unsigned long long acc2[8][8];
#pragma unroll
    for (int i = 0; i < 8; i++)
#pragma unroll
        for (int j = 0; j < 8; j++) acc2[i][j] = 0ull;

    float4 aprf[4], bprf[4];

    // preload step 0
#pragma unroll
    for (int i = 0; i < 4; i++) {
        aprf[i] = *(const float4*)(xg + (size_t)lr[i] * V_ + lk[i]);
        bprf[i] = *(const float4*)(wg + (size_t)lr[i] * V_ + lk[i]);
    }
#pragma unroll
    for (int i = 0; i < 4; i++) {
        As[lk[i] + 0][lr[i]] = aprf[i].x;
        As[lk[i] + 1][lr[i]] = aprf[i].y;
        As[lk[i] + 2][lr[i]] = aprf[i].z;
        As[lk[i] + 3][lr[i]] = aprf[i].w;
        Bs[lk[i] + 0][lr[i]] = bprf[i].x;
        Bs[lk[i] + 1][lr[i]] = bprf[i].y;
        Bs[lk[i] + 2][lr[i]] = bprf[i].z;
        Bs[lk[i] + 3][lr[i]] = bprf[i].w;
    }
    __syncthreads();

    for (int s = 0; s < nsteps; ++s) {
        // prefetch next tile into registers (overlaps compute)
        if (s + 1 < nsteps) {
            const float* xs = xg + (size_t)(s + 1) * BK;
            const float* ws = wg + (size_t)(s + 1) * BK;
#pragma unroll
            for (int i = 0; i < 4; i++) {
                aprf[i] = *(const float4*)(xs + (size_t)lr[i] * V_ + lk[i]);
                bprf[i] = *(const float4*)(ws + (size_t)lr[i] * V_ + lk[i]);
            }
        }

#pragma unroll
        for (int k = 0; k < BK; k++) {
            const float4 a0 = *(const float4*)&As[k][m0];
            const float4 a1 = *(const float4*)&As[k][m0 + 4];
            // b pairs come packed for free from 128-bit shared loads
            const ulonglong2 bq0 = *(const ulonglong2*)&Bs[k][n0];
            const ulonglong2 bq1 = *(const ulonglong2*)&Bs[k][n0 + 4];
            const ulonglong2 bq2 = *(const ulonglong2*)&Bs[k][n0 + 8];
            const ulonglong2 bq3 = *(const ulonglong2*)&Bs[k][n0 + 12];
            const unsigned long long bv2[8] = {bq0.x, bq0.y, bq1.x, bq1.y,
                                               bq2.x, bq2.y, bq3.x, bq3.y};

            const float av[8] = {a0.x, a0.y, a0.z, a0.w, a1.x, a1.y, a1.z, a1.w};
            unsigned long long av2[8];
#pragma unroll
            for (int i = 0; i < 8; i++) DUP_F32X2(av2[i], av[i]);

#pragma unroll
            for (int i = 0; i < 8; i++)
#pragma unroll
                for (int j = 0; j < 8; j++)
                    FFMA2(acc2[i][j], av2[i], bv2[j]);
        }
        __syncthreads();

        if (s + 1 < nsteps) {
#pragma unroll
            for (int i = 0; i < 4; i++) {
                As[lk[i] + 0][lr[i]] = aprf[i].x;
                As[lk[i] + 1][lr[i]] = aprf[i].y;
                As[lk[i] + 2][lr[i]] = aprf[i].z;
                As[lk[i] + 3][lr[i]] = aprf[i].w;
                Bs[lk[i] + 0][lr[i]] = bprf[i].x;
                Bs[lk[i] + 1][lr[i]] = bprf[i].y;
                Bs[lk[i] + 2][lr[i]] = bprf[i].z;
                Bs[lk[i] + 3][lr[i]] = bprf[i].w;
            }
            __syncthreads();
        }
    }

    // epilogue: packed pairs are already in output (n-contiguous) order
    float* op = g_scratch + (size_t)split * (B_ * E_)
              + (size_t)(brow * BM + m0) * E_ + (bcol * BN + n0);
#pragma unroll
    for (int i = 0; i < 8; i++) {
        ulonglong2 v0 = {acc2[i][0], acc2[i][1]};
        ulonglong2 v1 = {acc2[i][2], acc2[i][3]};
        ulonglong2 v2 = {acc2[i][4], acc2[i][5]};
        ulonglong2 v3 = {acc2[i][6], acc2[i][7]};
        *(ulonglong2*)(op + (size_t)i * E_)      = v0;
        *(ulonglong2*)(op + (size_t)i * E_ + 4)  = v1;
        *(ulonglong2*)(op + (size_t)i * E_ + 8)  = v2;
        *(ulonglong2*)(op + (size_t)i * E_ + 12) = v3;
    }
}

// ---------------------------------------------------------------------------
// Kernel 2: deterministic split-K reduction + bias -> g_emb (float4, high MLP)
// 65536 float4 elements; grid 256 x 256 threads.
// ---------------------------------------------------------------------------
__global__ __launch_bounds__(256) void reduce_bias_kernel(const float* __restrict__ bias)
{
    const int idx = blockIdx.x * blockDim.x + threadIdx.x;   // < B_*E_/4
    const float4* sc = (const float4*)g_scratch;
    float4 s = make_float4(0.f, 0.f, 0.f, 0.f);
#pragma unroll
    for (int sp = 0; sp < SPLITS; sp++) {
        const float4 v = sc[(size_t)sp * (B_ * E_ / 4) + idx];
        s.x += v.x; s.y += v.y; s.z += v.z; s.w += v.w;
    }
    const float4 bb = ((const float4*)bias)[idx & (E_ / 4 - 1)];
    s.x += bb.x; s.y += bb.y; s.z += bb.z; s.w += bb.w;
    ((float4*)g_emb)[idx] = s;
}

// ---------------------------------------------------------------------------
// Kernel 3: per-path dots, signed sigmoid, product. One block (4 warps) per
// batch row; warps split the 17 path nodes (5,4,4,4); deterministic combine.
// ---------------------------------------------------------------------------
__global__ __launch_bounds__(128) void path_prod_kernel(
    const float* __restrict__ pv, const int* __restrict__ signs,
    float* __restrict__ out)
{
    __shared__ float part[4];
    const int warp = threadIdx.x >> 5;
    const int lane = threadIdx.x & 31;
    const int b    = blockIdx.x;

    float e[8];
#pragma unroll
    for (int j = 0; j < 8; j++)
        e[j] = g_emb[b * E_ + lane + 32 * j];

    const int l0 = (warp == 0) ? 0 : (5 + (warp - 1) * 4);
    const int l1 = (warp == 0) ? 5 : (l0 + 4);

    float prod = 1.f;
#pragma unroll 1
    for (int l = l0; l < l1; l++) {
        const float* p = pv + ((size_t)b * L_ + l) * E_;
        float d = 0.f;
#pragma unroll
        for (int j = 0; j < 8; j++)
            d += p[lane + 32 * j] * e[j];
#pragma unroll
        for (int off = 16; off; off >>= 1)
            d += __shfl_xor_sync(0xFFFFFFFFu, d, off);

        const int   sg    = signs[b * L_ + l];
        const float logit = d * (float)(2 * sg - 1);

        float sgm;
        if (logit >= 0.f) {
            sgm = 1.f / (1.f + expf(-logit));
        } else {
            const float ex = expf(logit);     // stable tail, matches jax.nn.sigmoid
            sgm = ex / (1.f + ex);
        }
        prod *= sgm;
    }
    if (lane == 0) part[warp] = prod;
    __syncthreads();
    if (threadIdx.x == 0)
        out[b] = ((part[0] * part[1]) * part[2]) * part[3];
}

// ---------------------------------------------------------------------------
// Launch. Inputs (metadata order): x[B*V], W[E*V], b[E], path_vectors[B*L*E],
// path_signs[B*L] (int32). Output: float[B].
// ---------------------------------------------------------------------------
extern "C" void kernel_launch(void* const* d_in, const int* in_sizes, int n_in,
                              void* d_out, int out_size)
{
    const float* x     = (const float*)d_in[0];
    const float* W     = (const float*)d_in[1];
    const float* bias  = (const float*)d_in[2];
    const float* pv    = (const float*)d_in[3];
    const int*   signs = (const int*)  d_in[4];
    float*       out   = (float*)d_out;

    dim3 g1(B_ / BM, E_ / BN, SPLITS);   // (8, 2, 37) = 592 CTAs = 2 x 296
    gemm_splitk_kernel<<<g1, 128>>>(x, W);

    reduce_bias_kernel<<<(B_ * E_ / 4) / 256, 256>>>(bias);

    path_prod_kernel<<<B_, 128>>>(pv, signs, out);
}

// round 4
// speedup vs baseline: 1.4942x; 1.4942x over previous
#include <cuda_runtime.h>

// Problem shapes (fixed by the dataset)
#define B_  1024
#define V_  50000
#define E_  256
#define L_  17

// Split-K GEMM config: grid = 8 x 2 x 37 = 592 CTAs = exactly 2 waves of 296
#define SPLITS   37
#define KCHUNK   1360          // 85 BK-steps; last split: 50000-36*1360=1040 (65 steps)
#define BM       128
#define BN       128
#define BK       16

// Scratch: split-K partials [SPLITS][B][E], and reduced embedding [B][E].
__device__ __align__(128) float g_scratch[SPLITS * B_ * E_];
__device__ __align__(128) float g_emb[B_ * E_];

// Packed f32x2 FMA: d.lo += a.lo*b.lo; d.hi += a.hi*b.hi  (exact fp32 FMA x2)
#define FFMA2(d, a, b) \
    asm("fma.rn.f32x2 %0, %1, %2, %0;" : "+l"(d) : "l"(a), "l"(b))

#define DUP_F32X2(d, s) \
    asm("mov.b64 %0, {%1, %1};" : "=l"(d) : "f"(s))

// ---------------------------------------------------------------------------
// Kernel 1: split-K FP32 SGEMM via packed fma.rn.f32x2.
// x: [B, V] row-major, W: [E, V] row-major -> K-contiguous NT GEMM.
// Block tile 128x128, BK=16, 256 threads, 8x8 per-thread microtile
// (8x4 packed f32x2 accumulators). Double-buffered smem: one sync per step.
// ---------------------------------------------------------------------------
__global__ __launch_bounds__(256, 2) void gemm_splitk_kernel(
    const float* __restrict__ x, const float* __restrict__ W)
{
    __shared__ float As[2][BK][BM];   // k-major, double buffered
    __shared__ float Bs[2][BK][BN];

    const int tid   = threadIdx.x;
    const int brow  = blockIdx.x;          // 0..7   (B tiles)
    const int bcol  = blockIdx.y;          // 0..1   (E tiles)
    const int split = blockIdx.z;          // 0..36
    const int kbase = split * KCHUNK;
    const int nsteps = (split == SPLITS - 1) ? (V_ - (SPLITS - 1) * KCHUNK) / BK
                                             : KCHUNK / BK;

    const int trm = tid >> 4;              // 0..15
    const int tcn = tid & 15;              // 0..15
    const int m0  = trm * 8;
    const int n0  = tcn * 8;

    // global-load mapping: tile is 128 rows x 16 k-floats = 512 float4,
    // 256 threads -> 2 float4 each per operand.
    int lr[2], lk[2];
#pragma unroll
    for (int i = 0; i < 2; i++) {
        const int f = tid + i * 256;
        lr[i] = f >> 2;
        lk[i] = (f & 3) * 4;
    }

    const float* xg = x + (size_t)(brow * BM) * V_ + kbase;
    const float* wg = W + (size_t)(bcol * BN) * V_ + kbase;

    // 8x8 f32 microtile as 8x4 packed f32x2 (pairs along n)
    unsigned long long acc2[8][4];
#pragma unroll
    for (int i = 0; i < 8; i++)
#pragma unroll
        for (int j = 0; j < 4; j++) acc2[i][j] = 0ull;

    float4 aprf[2], bprf[2];

    // preload step 0 into buffer 0
#pragma unroll
    for (int i = 0; i < 2; i++) {
        aprf[i] = *(const float4*)(xg + (size_t)lr[i] * V_ + lk[i]);
        bprf[i] = *(const float4*)(wg + (size_t)lr[i] * V_ + lk[i]);
    }
#pragma unroll
    for (int i = 0; i < 2; i++) {
        As[0][lk[i] + 0][lr[i]] = aprf[i].x;
        As[0][lk[i] + 1][lr[i]] = aprf[i].y;
        As[0][lk[i] + 2][lr[i]] = aprf[i].z;
        As[0][lk[i] + 3][lr[i]] = aprf[i].w;
        Bs[0][lk[i] + 0][lr[i]] = bprf[i].x;
        Bs[0][lk[i] + 1][lr[i]] = bprf[i].y;
        Bs[0][lk[i] + 2][lr[i]] = bprf[i].z;
        Bs[0][lk[i] + 3][lr[i]] = bprf[i].w;
    }
    __syncthreads();

    int buf = 0;
    for (int s = 0; s < nsteps; ++s) {
        // prefetch next tile into registers (overlaps compute)
        if (s + 1 < nsteps) {
            const float* xs = xg + (size_t)(s + 1) * BK;
            const float* ws = wg + (size_t)(s + 1) * BK;
#pragma unroll
            for (int i = 0; i < 2; i++) {
                aprf[i] = *(const float4*)(xs + (size_t)lr[i] * V_ + lk[i]);
                bprf[i] = *(const float4*)(ws + (size_t)lr[i] * V_ + lk[i]);
            }
        }

#pragma unroll
        for (int k = 0; k < BK; k++) {
            const float4 a0 = *(const float4*)&As[buf][k][m0];
            const float4 a1 = *(const float4*)&As[buf][k][m0 + 4];
            // b pairs come packed for free from 128-bit shared loads
            const ulonglong2 bq0 = *(const ulonglong2*)&Bs[buf][k][n0];
            const ulonglong2 bq1 = *(const ulonglong2*)&Bs[buf][k][n0 + 4];
            const unsigned long long bv2[4] = {bq0.x, bq0.y, bq1.x, bq1.y};

            const float av[8] = {a0.x, a0.y, a0.z, a0.w, a1.x, a1.y, a1.z, a1.w};
            unsigned long long av2[8];
#pragma unroll
            for (int i = 0; i < 8; i++) DUP_F32X2(av2[i], av[i]);

#pragma unroll
            for (int i = 0; i < 8; i++)
#pragma unroll
                for (int j = 0; j < 4; j++)
                    FFMA2(acc2[i][j], av2[i], bv2[j]);
        }

        // write prefetched tile into the other buffer; one sync per step
        if (s + 1 < nsteps) {
            const int nb = buf ^ 1;
#pragma unroll
            for (int i = 0; i < 2; i++) {
                As[nb][lk[i] + 0][lr[i]] = aprf[i].x;
                As[nb][lk[i] + 1][lr[i]] = aprf[i].y;
                As[nb][lk[i] + 2][lr[i]] = aprf[i].z;
                As[nb][lk[i] + 3][lr[i]] = aprf[i].w;
                Bs[nb][lk[i] + 0][lr[i]] = bprf[i].x;
                Bs[nb][lk[i] + 1][lr[i]] = bprf[i].y;
                Bs[nb][lk[i] + 2][lr[i]] = bprf[i].z;
                Bs[nb][lk[i] + 3][lr[i]] = bprf[i].w;
            }
            __syncthreads();
            buf = nb;
        }
    }

    // epilogue: packed pairs are already in output (n-contiguous) order
    float* op = g_scratch + (size_t)split * (B_ * E_)
              + (size_t)(brow * BM + m0) * E_ + (bcol * BN + n0);
#pragma unroll
    for (int i = 0; i < 8; i++) {
        ulonglong2 v0 = {acc2[i][0], acc2[i][1]};
        ulonglong2 v1 = {acc2[i][2], acc2[i][3]};
        *(ulonglong2*)(op + (size_t)i * E_)     = v0;
        *(ulonglong2*)(op + (size_t)i * E_ + 4) = v1;
    }
}

// ---------------------------------------------------------------------------
// Kernel 2: deterministic split-K reduction + bias -> g_emb (float4, high MLP)
// ---------------------------------------------------------------------------
__global__ __launch_bounds__(256) void reduce_bias_kernel(const float* __restrict__ bias)
{
    const int idx = blockIdx.x * blockDim.x + threadIdx.x;   // < B_*E_/4
    const float4* sc = (const float4*)g_scratch;
    float4 s = make_float4(0.f, 0.f, 0.f, 0.f);
#pragma unroll
    for (int sp = 0; sp < SPLITS; sp++) {
        const float4 v = sc[(size_t)sp * (B_ * E_ / 4) + idx];
        s.x += v.x; s.y += v.y; s.z += v.z; s.w += v.w;
    }
    const float4 bb = ((const float4*)bias)[idx & (E_ / 4 - 1)];
    s.x += bb.x; s.y += bb.y; s.z += bb.z; s.w += bb.w;
    ((float4*)g_emb)[idx] = s;
}

// ---------------------------------------------------------------------------
// Kernel 3: per-path dots, signed sigmoid, product. One block (4 warps) per
// batch row; warps split the 17 path nodes (5,4,4,4); deterministic combine.
// ---------------------------------------------------------------------------
__global__ __launch_bounds__(128) void path_prod_kernel(
    const float* __restrict__ pv, const int* __restrict__ signs,
    float* __restrict__ out)
{
    __shared__ float part[4];
    const int warp = threadIdx.x >> 5;
    const int lane = threadIdx.x & 31;
    const int b    = blockIdx.x;

    float e[8];
#pragma unroll
    for (int j = 0; j < 8; j++)
        e[j] = g_emb[b * E_ + lane + 32 * j];

    const int l0 = (warp == 0) ? 0 : (5 + (warp - 1) * 4);
    const int l1 = (warp == 0) ? 5 : (l0 + 4);

    float prod = 1.f;
#pragma unroll 1
    for (int l = l0; l < l1; l++) {
        const float* p = pv + ((size_t)b * L_ + l) * E_;
        float d = 0.f;
#pragma unroll
        for (int j = 0; j < 8; j++)
            d += p[lane + 32 * j] * e[j];
#pragma unroll
        for (int off = 16; off; off >>= 1)
            d += __shfl_xor_sync(0xFFFFFFFFu, d, off);

        const int   sg    = signs[b * L_ + l];
        const float logit = d * (float)(2 * sg - 1);

        float sgm;
        if (logit >= 0.f) {
            sgm = 1.f / (1.f + expf(-logit));
        } else {
            const float ex = expf(logit);     // stable tail, matches jax.nn.sigmoid
            sgm = ex / (1.f + ex);
        }
        prod *= sgm;
    }
    if (lane == 0) part[warp] = prod;
    __syncthreads();
    if (threadIdx.x == 0)
        out[b] = ((part[0] * part[1]) * part[2]) * part[3];
}

// ---------------------------------------------------------------------------
// Launch. Inputs (metadata order): x[B*V], W[E*V], b[E], path_vectors[B*L*E],
// path_signs[B*L] (int32). Output: float[B].
// ---------------------------------------------------------------------------
extern "C" void kernel_launch(void* const* d_in, const int* in_sizes, int n_in,
                              void* d_out, int out_size)
{
    const float* x     = (const float*)d_in[0];
    const float* W     = (const float*)d_in[1];
    const float* bias  = (const float*)d_in[2];
    const float* pv    = (const float*)d_in[3];
    const int*   signs = (const int*)  d_in[4];
    float*       out   = (float*)d_out;

    dim3 g1(B_ / BM, E_ / BN, SPLITS);   // (8, 2, 37) = 592 CTAs = 2 x 296
    gemm_splitk_kernel<<<g1, 256>>>(x, W);

    reduce_bias_kernel<<<(B_ * E_ / 4) / 256, 256>>>(bias);

    path_prod_kernel<<<B_, 128>>>(pv, signs, out);
}

// round 7
// speedup vs baseline: 2.5560x; 1.7106x over previous
#include <cuda_runtime.h>
#include <cstdint>

// Problem shapes (fixed by the dataset)
#define B_  1024
#define V_  50000
#define E_  256
#define L_  17

// HMMA GEMM config
#define SPLITS   9              // grid (8,2,9) = 144 CTAs ~ 1 wave
#define BKC      32             // k elements per chunk
#define NCHUNKS  1563           // ceil(50000/32); last chunk has 16 valid cols
#define MTILE    128
#define NTILE    128
#define TILE     8192           // one 128x32 bf16 tile
#define STAGE    (4 * TILE)     // A_hi A_mid B_hi B_mid
#define SMEM_REQ (2 * STAGE)    // 64 KB double-buffered

__device__ __align__(128) float g_scratch[SPLITS * B_ * E_];
__device__ __align__(128) float g_emb[B_ * E_];

// ---------------------------------------------------------------------------
// Helpers
// ---------------------------------------------------------------------------
__device__ __forceinline__ uint32_t smem_u32(const void* p) {
    uint32_t a;
    asm("{ .reg .u64 t; cvta.to.shared.u64 t, %1; cvt.u32.u64 %0, t; }"
        : "=r"(a) : "l"(p));
    return a;
}

// Tile layout: 8x8 bf16 blocks (128B each), block (br, bc) at (br*4+bc)*128.
// Row j of a block lives at 16B slot (j ^ (br&7) ^ ((bc&2)<<1)):
//  - ldmatrix: 8 lanes of one matrix -> 8 distinct slots -> conflict-free
//  - STS.128 fill: each 8-lane phase covers all 8 slots  -> conflict-free
// (Numerically validated on-device in R6: HH path exact.)
__device__ __forceinline__ uint32_t toff(int r, int c) {
    const int br = r >> 3, bc = c >> 3;
    const int slot = (r & 7) ^ (br & 7) ^ ((bc & 2) << 1);
    return (uint32_t)((((br << 2) + bc) << 7) + (slot << 4) + ((c & 7) << 1));
}

#define LDSM4(d, addr) \
    asm volatile("ldmatrix.sync.aligned.m8n8.x4.shared.b16 {%0,%1,%2,%3}, [%4];" \
        : "=r"((d)[0]), "=r"((d)[1]), "=r"((d)[2]), "=r"((d)[3]) : "r"(addr))

// accumulate into d (d += a*b)
#define MMA16816(c, a, b0, b1) \
    asm volatile("mma.sync.aligned.m16n8k16.row.col.f32.bf16.bf16.f32 " \
        "{%0,%1,%2,%3}, {%4,%5,%6,%7}, {%8,%9}, {%0,%1,%2,%3};" \
        : "+f"((c)[0]), "+f"((c)[1]), "+f"((c)[2]), "+f"((c)[3]) \
        : "r"((a)[0]), "r"((a)[1]), "r"((a)[2]), "r"((a)[3]), "r"(b0), "r"(b1))

// overwrite d with a*b (zero C operand) -- seeds a fresh accumulation window
#define MMA16816_ZC(c, a, b0, b1, z) \
    asm volatile("mma.sync.aligned.m16n8k16.row.col.f32.bf16.bf16.f32 " \
        "{%0,%1,%2,%3}, {%4,%5,%6,%7}, {%8,%9}, {%10,%11,%12,%13};" \
        : "=f"((c)[0]), "=f"((c)[1]), "=f"((c)[2]), "=f"((c)[3]) \
        : "r"((a)[0]), "r"((a)[1]), "r"((a)[2]), "r"((a)[3]), "r"(b0), "r"(b1), \
          "f"(z), "f"(z), "f"(z), "f"(z))

#define STS128(addr, v) \
    asm volatile("st.shared.v4.b32 [%0], {%1, %2, %3, %4};" \
        :: "r"(addr), "r"((v).x), "r"((v).y), "r"((v).z), "r"((v).w) : "memory")

// 2-way bf16 split of 8 fp32 values -> two bf16x2-packed uint4.
// x = hi + mid + s, |s| <~ 2^-18 |x| (RN residual, random sign)
__device__ __forceinline__ void split2(const float f[8], uint4& H, uint4& M) {
    uint32_t hw[4], mw[4];
#pragma unroll
    for (int i = 0; i < 4; i++) {
        const float f0 = f[2 * i], f1 = f[2 * i + 1];
        uint32_t hp;
        asm("cvt.rn.bf16x2.f32 %0, %1, %2;" : "=r"(hp) : "f"(f1), "f"(f0));
        const float h0 = __uint_as_float(hp << 16);
        const float h1 = __uint_as_float(hp & 0xFFFF0000u);
        const float r0 = f0 - h0, r1 = f1 - h1;   // exact (Sterbenz)
        uint32_t mp;
        asm("cvt.rn.bf16x2.f32 %0, %1, %2;" : "=r"(mp) : "f"(r1), "f"(r0));
        hw[i] = hp; mw[i] = mp;
    }
    H = make_uint4(hw[0], hw[1], hw[2], hw[3]);
    M = make_uint4(mw[0], mw[1], mw[2], mw[3]);
}

// ---------------------------------------------------------------------------
// Kernel 1: split-K GEMM via 4-pass bf16-split mma.sync (HMMA), two-level
// accumulation (temp acc flushed to fp32 main acc every 2 chunks) to defeat
// tensor-core truncation bias. Grid (8, 2, SPLITS), 256 threads.
// ---------------------------------------------------------------------------
__global__ __launch_bounds__(256, 1) void gemm_hmma_kernel(
    const float* __restrict__ x, const float* __restrict__ W)
{
    extern __shared__ __align__(1024) char smem[];
    const uint32_t sm0 = smem_u32(smem);

    const int tid  = threadIdx.x;
    const int lane = tid & 31;
    const int wid  = tid >> 5;
    const int wm   = wid >> 1;            // 0..3 -> m offset 32*wm
    const int wn   = wid & 1;             // 0..1 -> n offset 64*wn

    const int brow  = blockIdx.x;         // 0..7
    const int bcol  = blockIdx.y;         // 0..1
    const int split = blockIdx.z;         // 0..SPLITS-1
    const int c0 = (split * NCHUNKS) / SPLITS;
    const int c1 = ((split + 1) * NCHUNKS) / SPLITS;

    const float* xrow = x + (size_t)(brow * MTILE) * V_;
    const float* wrow = W + (size_t)(bcol * NTILE) * V_;

    // fill mapping: thread handles row fr, 16 consecutive floats (half fh)
    const int fr = tid >> 1;              // 0..127
    const int fh = tid & 1;               // 0..1

    // ldmatrix lane address components
    const int jrA = ((lane >> 3) & 1) * 8 + (lane & 7);   // A row-in-frag
    const int cA  = (lane >> 4) * 8;                      // A col-in-frag
    const int nB  = (lane >> 4) * 8 + (lane & 7);         // B n-in-frag
    const int cB  = ((lane >> 3) & 1) * 8;                // B k-in-frag

    float accm[2][8][4];                  // main accumulator (RN FADD)
    float acct[2][8][4];                  // HMMA window accumulator
#pragma unroll
    for (int i = 0; i < 2; i++)
#pragma unroll
        for (int j = 0; j < 8; j++)
#pragma unroll
            for (int q = 0; q < 4; q++) accm[i][j][q] = 0.f;

    const float fz = 0.f;
    float fA[16], fB[16];

    auto load_raw = [&](int c) {
        const int kbase = c * BKC;
        const float* pa = xrow + (size_t)fr * V_ + kbase + fh * 16;
        const float* pb = wrow + (size_t)fr * V_ + kbase + fh * 16;
        if (kbase + BKC <= V_) {
#pragma unroll
            for (int i = 0; i < 4; i++) {
                const float4 va = ((const float4*)pa)[i];
                const float4 vb = ((const float4*)pb)[i];
                fA[4 * i + 0] = va.x; fA[4 * i + 1] = va.y;
                fA[4 * i + 2] = va.z; fA[4 * i + 3] = va.w;
                fB[4 * i + 0] = vb.x; fB[4 * i + 1] = vb.y;
                fB[4 * i + 2] = vb.z; fB[4 * i + 3] = vb.w;
            }
        } else {
#pragma unroll
            for (int e = 0; e < 16; e++) {
                const bool ok = (kbase + fh * 16 + e) < V_;
                fA[e] = ok ? pa[e] : 0.f;
                fB[e] = ok ? pb[e] : 0.f;
            }
        }
    };

    auto sts_convert = [&](uint32_t sb) {
#pragma unroll
        for (int g = 0; g < 2; g++) {
            const int bc = 2 * fh + g;
            const uint32_t o = ((((fr >> 3) << 2) + bc) << 7)
                + ((((fr & 7) ^ ((fr >> 3) & 7) ^ ((bc & 2) << 1))) << 4);
            uint4 H, M;
            split2(fA + 8 * g, H, M);
            STS128(sb + 0 * TILE + o, H);
            STS128(sb + 1 * TILE + o, M);
            split2(fB + 8 * g, H, M);
            STS128(sb + 2 * TILE + o, H);
            STS128(sb + 3 * TILE + o, M);
        }
    };

    // prologue: fill stage 0
    load_raw(c0);
    sts_convert(sm0);
    __syncthreads();

    for (int c = c0; c < c1; ++c) {
        const int li = c - c0;
        const uint32_t sb = sm0 + (uint32_t)(li & 1) * STAGE;
        const bool more     = (c + 1 < c1);
        const bool winStart = ((li & 1) == 0);          // 2-chunk windows
        const bool winEnd   = ((li & 1) == 1) || !more; // flush at end/last

        if (more) load_raw(c + 1);

        // ---- compute this chunk: 4 passes (A{H,M} x B{H,M}), k = 0, 16 ----
#pragma unroll
        for (int k = 0; k < BKC; k += 16) {
            uint32_t a[2][2][4];
#pragma unroll
            for (int lv = 0; lv < 2; lv++)
#pragma unroll
                for (int mt = 0; mt < 2; mt++)
                    LDSM4(a[lv][mt],
                          sb + lv * TILE + toff(wm * 32 + mt * 16 + jrA, k + cA));

#pragma unroll
            for (int lb = 0; lb < 2; lb++) {
                uint32_t b[4][4];
#pragma unroll
                for (int ng = 0; ng < 4; ng++)
                    LDSM4(b[ng],
                          sb + (2 + lb) * TILE + toff(wn * 64 + ng * 16 + nB, k + cB));

#pragma unroll
                for (int la = 0; la < 2; la++) {
                    const bool seed = winStart && (k == 0) && (lb == 0) && (la == 0);
#pragma unroll
                    for (int mt = 0; mt < 2; mt++)
#pragma unroll
                        for (int nt = 0; nt < 8; nt++) {
                            if (seed)
                                MMA16816_ZC(acct[mt][nt], a[la][mt],
                                            b[nt >> 1][(nt & 1) * 2],
                                            b[nt >> 1][(nt & 1) * 2 + 1], fz);
                            else
                                MMA16816(acct[mt][nt], a[la][mt],
                                         b[nt >> 1][(nt & 1) * 2],
                                         b[nt >> 1][(nt & 1) * 2 + 1]);
                        }
                }
            }
        }

        // window flush: RN fp32 adds into the main accumulator
        if (winEnd) {
#pragma unroll
            for (int mt = 0; mt < 2; mt++)
#pragma unroll
                for (int nt = 0; nt < 8; nt++)
#pragma unroll
                    for (int q = 0; q < 4; q++)
                        accm[mt][nt][q] += acct[mt][nt][q];
        }

        if (more) sts_convert(sm0 + (uint32_t)((li + 1) & 1) * STAGE);
        __syncthreads();
    }

    // epilogue: write fp32 partials
    float* base = g_scratch + (size_t)split * (B_ * E_);
#pragma unroll
    for (int mt = 0; mt < 2; mt++)
#pragma unroll
        for (int nt = 0; nt < 8; nt++) {
            const int row = brow * MTILE + wm * 32 + mt * 16 + (lane >> 2);
            const int col = bcol * NTILE + wn * 64 + nt * 8 + (lane & 3) * 2;
            float2 v0 = make_float2(accm[mt][nt][0], accm[mt][nt][1]);
            float2 v1 = make_float2(accm[mt][nt][2], accm[mt][nt][3]);
            *(float2*)&base[(size_t)row * E_ + col]       = v0;
            *(float2*)&base[(size_t)(row + 8) * E_ + col] = v1;
        }
}

// ---------------------------------------------------------------------------
// Kernel 2: deterministic split-K reduction + bias -> g_emb (float4, high MLP)
// ---------------------------------------------------------------------------
__global__ __launch_bounds__(256) void reduce_bias_kernel(const float* __restrict__ bias)
{
    const int idx = blockIdx.x * blockDim.x + threadIdx.x;   // < B_*E_/4
    const float4* sc = (const float4*)g_scratch;
    float4 s = make_float4(0.f, 0.f, 0.f, 0.f);
#pragma unroll
    for (int sp = 0; sp < SPLITS; sp++) {
        const float4 v = sc[(size_t)sp * (B_ * E_ / 4) + idx];
        s.x += v.x; s.y += v.y; s.z += v.z; s.w += v.w;
    }
    const float4 bb = ((const float4*)bias)[idx & (E_ / 4 - 1)];
    s.x += bb.x; s.y += bb.y; s.z += bb.z; s.w += bb.w;
    ((float4*)g_emb)[idx] = s;
}

// ---------------------------------------------------------------------------
// Kernel 3: per-path dots, signed sigmoid, product. One block (4 warps) per
// batch row; warps split the 17 path nodes (5,4,4,4); deterministic combine.
// ---------------------------------------------------------------------------
__global__ __launch_bounds__(128) void path_prod_kernel(
    const float* __restrict__ pv, const int* __restrict__ signs,
    float* __restrict__ out)
{
    __shared__ float part[4];
    const int warp = threadIdx.x >> 5;
    const int lane = threadIdx.x & 31;
    const int b    = blockIdx.x;

    float e[8];
#pragma unroll
    for (int j = 0; j < 8; j++)
        e[j] = g_emb[b * E_ + lane + 32 * j];

    const int l0 = (warp == 0) ? 0 : (5 + (warp - 1) * 4);
    const int l1 = (warp == 0) ? 5 : (l0 + 4);

    float prod = 1.f;
#pragma unroll 1
    for (int l = l0; l < l1; l++) {
        const float* p = pv + ((size_t)b * L_ + l) * E_;
        float d = 0.f;
#pragma unroll
        for (int j = 0; j < 8; j++)
            d += p[lane + 32 * j] * e[j];
#pragma unroll
        for (int off = 16; off; off >>= 1)
            d += __shfl_xor_sync(0xFFFFFFFFu, d, off);

        const int   sg    = signs[b * L_ + l];
        const float logit = d * (float)(2 * sg - 1);

        float sgm;
        if (logit >= 0.f) {
            sgm = 1.f / (1.f + expf(-logit));
        } else {
            const float ex = expf(logit);     // stable tail, matches jax.nn.sigmoid
            sgm = ex / (1.f + ex);
        }
        prod *= sgm;
    }
    if (lane == 0) part[warp] = prod;
    __syncthreads();
    if (threadIdx.x == 0)
        out[b] = ((part[0] * part[1]) * part[2]) * part[3];
}

// ---------------------------------------------------------------------------
// Launch. Inputs (metadata order): x[B*V], W[E*V], b[E], path_vectors[B*L*E],
// path_signs[B*L] (int32). Output: float[B].
// ---------------------------------------------------------------------------
extern "C" void kernel_launch(void* const* d_in, const int* in_sizes, int n_in,
                              void* d_out, int out_size)
{
    const float* x     = (const float*)d_in[0];
    const float* W     = (const float*)d_in[1];
    const float* bias  = (const float*)d_in[2];
    const float* pv    = (const float*)d_in[3];
    const int*   signs = (const int*)  d_in[4];
    float*       out   = (float*)d_out;

    // idempotent attribute set (not a stream op; capture-safe)
    cudaFuncSetAttribute(gemm_hmma_kernel,
                         cudaFuncAttributeMaxDynamicSharedMemorySize, SMEM_REQ);

    dim3 g1(B_ / MTILE, E_ / NTILE, SPLITS);   // (8, 2, 9) = 144 CTAs
    gemm_hmma_kernel<<<g1, 256, SMEM_REQ>>>(x, W);

    reduce_bias_kernel<<<(B_ * E_ / 4) / 256, 256>>>(bias);

    path_prod_kernel<<<B_, 128>>>(pv, signs, out);
}